// round 9
// baseline (speedup 1.0000x reference)
#include <cuda_runtime.h>
#include <cuda_bf16.h>

// 3x3 median filter, zero padding, exact median of 9.
// x: (32, 3, 512, 512) fp32 -> 96 images of 512x512.
//
// Thread = 4 columns x 4 output rows (16 px), register-resident.
// Same algorithm & instruction order as the round-6 kernel (best so far),
// with 32-bit indexing and __launch_bounds__(256,6) to cut registers to
// <=42 and raise occupancy from 40 to 48 warps/SM.
// Zero-padding via clamped addresses + exact 0/1 FMUL masks (fma pipe).
// Exact min/max network, ~17.5 FMNMX/px, 1.125 loads/px.

#define W 512
#define H 512
#define NIMG 96

__device__ __forceinline__ float med3(float a, float b, float c) {
    return fmaxf(fminf(a, b), fminf(fmaxf(a, b), c));
}

// Load one row's 6-column window (cb-1 .. cb+4), clamped addresses.
template <bool MASK_ROW>
__device__ __forceinline__ void load_row(const float* __restrict__ rowp,
                                         int cb, int cl, int cr,
                                         float ml, float mr, float mrow,
                                         float* c) {
    const float4 v = *reinterpret_cast<const float4*>(rowp + cb);
    const float l = __ldg(rowp + cl);
    const float r = __ldg(rowp + cr);
    if (MASK_ROW) {
        c[0] = l * (ml * mrow);
        c[1] = v.x * mrow; c[2] = v.y * mrow;
        c[3] = v.z * mrow; c[4] = v.w * mrow;
        c[5] = r * (mr * mrow);
    } else {
        c[0] = l * ml;
        c[1] = v.x; c[2] = v.y; c[3] = v.z; c[4] = v.w;
        c[5] = r * mr;
    }
}

// Emit one output row: insert row a into (mn, mx) = sort2 of the other two
// rows, combine 3-wide windows with pair sharing, store one float4.
__device__ __forceinline__ void emit_row(const float* a, const float* mn,
                                         const float* mx,
                                         float* __restrict__ outp) {
    float lo[6], mi[6], hi[6];
    #pragma unroll
    for (int i = 0; i < 6; i++) {
        lo[i] = fminf(a[i], mn[i]);
        hi[i] = fmaxf(a[i], mx[i]);
        mi[i] = fmaxf(mn[i], fminf(a[i], mx[i]));
    }
    float o[4];
    #pragma unroll
    for (int t = 0; t < 2; t++) {
        const int i = 2 * t + 1;
        const float A = fmaxf(lo[i], lo[i + 1]);
        const float B = fminf(hi[i], hi[i + 1]);
        const float n = fminf(mi[i], mi[i + 1]);
        const float m = fmaxf(mi[i], mi[i + 1]);
        o[2 * t]     = med3(fmaxf(A, lo[2 * t]),
                            fmaxf(n, fminf(m, mi[2 * t])),
                            fminf(B, hi[2 * t]));
        o[2 * t + 1] = med3(fmaxf(A, lo[2 * t + 3]),
                            fminf(m, fmaxf(n, mi[2 * t + 3])),
                            fminf(B, hi[2 * t + 3]));
    }
    float4 res; res.x = o[0]; res.y = o[1]; res.z = o[2]; res.w = o[3];
    *reinterpret_cast<float4*>(outp) = res;
}

__global__ void __launch_bounds__(256, 6)
median3x3_kernel(const float* __restrict__ x, float* __restrict__ out) {
    const int tid = blockIdx.x * blockDim.x + threadIdx.x;
    const int cb  = (tid & 127) << 2;          // column base (0..508)
    const int sid = tid >> 7;                  // strip id
    const int y0  = (sid & 127) << 2;          // strip top output row (step 4)
    const int ibase = (sid >> 7) * (H * W);    // image base (max 24.9M, int ok)
    const float* img = x + ibase;
    float* oimg = out + ibase;

    const int cl = (cb == 0)     ? 0     : cb - 1;
    const int cr = (cb == W - 4) ? W - 1 : cb + 4;
    const float ml = (cb > 0)     ? 1.0f : 0.0f;
    const float mr = (cb < W - 4) ? 1.0f : 0.0f;

    const float mt = (y0 > 0)     ? 1.0f : 0.0f;   // row y0-1 valid
    const float mb = (y0 < H - 4) ? 1.0f : 0.0f;   // row y0+4 valid

    // Base pointer for the always-in-bounds rows; clamped top/bottom rows.
    const float* pm = img + y0 * W;
    const float* pt = img + (y0 > 0 ? y0 - 1 : 0) * W;
    const float* pb = img + (y0 + 4 < H ? y0 + 4 : H - 1) * W;

    float ra[6], rb[6], rc[6], rd[6], re[6], rf[6];
    float mn[6], mx[6];

    // --- pair 0: output rows y0, y0+1 (inputs y0-1 .. y0+2) ---
    load_row<true >(pt,         cb, cl, cr, ml, mr, mt,   ra);
    load_row<false>(pm,         cb, cl, cr, ml, mr, 1.0f, rb);
    load_row<false>(pm + W,     cb, cl, cr, ml, mr, 1.0f, rc);
    load_row<false>(pm + 2 * W, cb, cl, cr, ml, mr, 1.0f, rd);

    #pragma unroll
    for (int i = 0; i < 6; i++) {              // rb dead after this
        mn[i] = fminf(rb[i], rc[i]);
        mx[i] = fmaxf(rb[i], rc[i]);
    }
    float* op = oimg + y0 * W + cb;
    emit_row(ra, mn, mx, op);                  // ra dead
    emit_row(rd, mn, mx, op + W);              // mn,mx dead

    // --- pair 1: output rows y0+2, y0+3 (inputs y0+1 .. y0+4) ---
    load_row<false>(pm + 3 * W, cb, cl, cr, ml, mr, 1.0f, re);
    load_row<true >(pb,         cb, cl, cr, ml, mr, mb,   rf);

    #pragma unroll
    for (int i = 0; i < 6; i++) {
        mn[i] = fminf(rd[i], re[i]);
        mx[i] = fmaxf(rd[i], re[i]);
    }
    emit_row(rc, mn, mx, op + 2 * W);
    emit_row(rf, mn, mx, op + 3 * W);
}

extern "C" void kernel_launch(void* const* d_in, const int* in_sizes, int n_in,
                              void* d_out, int out_size) {
    const float* x = (const float*)d_in[0];
    float* out = (float*)d_out;

    const int total_threads = (NIMG * H * W) / 16;   // 1,572,864
    const int block = 256;
    const int grid = total_threads / block;           // 6144
    median3x3_kernel<<<grid, block>>>(x, out);
}

// round 10
// speedup vs baseline: 1.1139x; 1.1139x over previous
#include <cuda_runtime.h>
#include <cuda_bf16.h>

// 3x3 median filter, zero padding, exact median of 9.
// x: (32, 3, 512, 512) fp32 -> 96 images of 512x512.
//
// Algorithm and instruction order identical to the round-6 best (35.1us):
// thread = 4 cols x 4 output rows, register-resident, two load batches,
// shared sort2 of middle rows, pair-shared sliding-window combine,
// exact min/max network (~14 FMNMX/px), masks on the fma pipe.
// Changes vs R6: 128-thread blocks (10 blocks/SM -> de-synchronized load
// stalls across more independent blocks) and streaming output stores
// (__stcs: keep input hot in L2 instead of write data).

#define W 512
#define H 512
#define NIMG 96

__device__ __forceinline__ float med3(float a, float b, float c) {
    return fmaxf(fminf(a, b), fminf(fmaxf(a, b), c));
}

// Load one row's 6-column window (cb-1 .. cb+4), clamped addresses.
template <bool MASK_ROW>
__device__ __forceinline__ void load_row(const float* __restrict__ rowp,
                                         int cb, int cl, int cr,
                                         float ml, float mr, float mrow,
                                         float* c) {
    const float4 v = *reinterpret_cast<const float4*>(rowp + cb);
    const float l = __ldg(rowp + cl);
    const float r = __ldg(rowp + cr);
    if (MASK_ROW) {
        c[0] = l * (ml * mrow);
        c[1] = v.x * mrow; c[2] = v.y * mrow;
        c[3] = v.z * mrow; c[4] = v.w * mrow;
        c[5] = r * (mr * mrow);
    } else {
        c[0] = l * ml;
        c[1] = v.x; c[2] = v.y; c[3] = v.z; c[4] = v.w;
        c[5] = r * mr;
    }
}

// Emit one output row: insert row a into (mn, mx) = sort2 of the other two
// rows, combine 3-wide windows with pair sharing, streaming-store a float4.
__device__ __forceinline__ void emit_row(const float* a, const float* mn,
                                         const float* mx,
                                         float* __restrict__ outp) {
    float lo[6], mi[6], hi[6];
    #pragma unroll
    for (int i = 0; i < 6; i++) {
        lo[i] = fminf(a[i], mn[i]);
        hi[i] = fmaxf(a[i], mx[i]);
        mi[i] = fmaxf(mn[i], fminf(a[i], mx[i]));
    }
    float o[4];
    #pragma unroll
    for (int t = 0; t < 2; t++) {
        const int i = 2 * t + 1;
        const float A = fmaxf(lo[i], lo[i + 1]);
        const float B = fminf(hi[i], hi[i + 1]);
        const float n = fminf(mi[i], mi[i + 1]);
        const float m = fmaxf(mi[i], mi[i + 1]);
        o[2 * t]     = med3(fmaxf(A, lo[2 * t]),
                            fmaxf(n, fminf(m, mi[2 * t])),
                            fminf(B, hi[2 * t]));
        o[2 * t + 1] = med3(fmaxf(A, lo[2 * t + 3]),
                            fminf(m, fmaxf(n, mi[2 * t + 3])),
                            fminf(B, hi[2 * t + 3]));
    }
    float4 res; res.x = o[0]; res.y = o[1]; res.z = o[2]; res.w = o[3];
    __stcs(reinterpret_cast<float4*>(outp), res);
}

__global__ void __launch_bounds__(128, 10)
median3x3_kernel(const float* __restrict__ x, float* __restrict__ out) {
    const int tid = blockIdx.x * 128 + threadIdx.x;
    const int cb  = (tid & 127) << 2;          // column base (0..508)
    const int sid = tid >> 7;                  // strip id
    const int y0  = (sid & 127) << 2;          // strip top output row (step 4)
    const size_t ibase = (size_t)(sid >> 7) * (H * W);
    const float* img = x + ibase;
    float* oimg = out + ibase;

    const int cl = (cb == 0)     ? 0     : cb - 1;
    const int cr = (cb == W - 4) ? W - 1 : cb + 4;
    const float ml = (cb > 0)     ? 1.0f : 0.0f;
    const float mr = (cb < W - 4) ? 1.0f : 0.0f;

    const float mt = (y0 > 0)     ? 1.0f : 0.0f;   // row y0-1 valid
    const float mb = (y0 < H - 4) ? 1.0f : 0.0f;   // row y0+4 valid

    float ra[6], rb[6], rc[6], rd[6], re[6], rf[6];
    float mn[6], mx[6];

    // --- pair 0: output rows y0, y0+1 (inputs y0-1 .. y0+2) ---
    load_row<true >(img + (y0 > 0 ? y0 - 1 : 0) * W, cb, cl, cr, ml, mr, mt, ra);
    load_row<false>(img + (y0    ) * W, cb, cl, cr, ml, mr, 1.0f, rb);
    load_row<false>(img + (y0 + 1) * W, cb, cl, cr, ml, mr, 1.0f, rc);
    load_row<false>(img + (y0 + 2) * W, cb, cl, cr, ml, mr, 1.0f, rd);

    #pragma unroll
    for (int i = 0; i < 6; i++) {              // rb dead after this
        mn[i] = fminf(rb[i], rc[i]);
        mx[i] = fmaxf(rb[i], rc[i]);
    }
    emit_row(ra, mn, mx, oimg + (size_t)y0 * W + cb);        // ra dead
    emit_row(rd, mn, mx, oimg + (size_t)(y0 + 1) * W + cb);  // mn,mx dead

    // --- pair 1: output rows y0+2, y0+3 (inputs y0+1 .. y0+4) ---
    load_row<false>(img + (y0 + 3) * W, cb, cl, cr, ml, mr, 1.0f, re);
    load_row<true >(img + (y0 + 4 < H ? y0 + 4 : H - 1) * W, cb, cl, cr, ml, mr, mb, rf);

    #pragma unroll
    for (int i = 0; i < 6; i++) {
        mn[i] = fminf(rd[i], re[i]);
        mx[i] = fmaxf(rd[i], re[i]);
    }
    emit_row(rc, mn, mx, oimg + (size_t)(y0 + 2) * W + cb);
    emit_row(rf, mn, mx, oimg + (size_t)(y0 + 3) * W + cb);
}

extern "C" void kernel_launch(void* const* d_in, const int* in_sizes, int n_in,
                              void* d_out, int out_size) {
    const float* x = (const float*)d_in[0];
    float* out = (float*)d_out;

    const int total_threads = (NIMG * H * W) / 16;   // 1,572,864
    const int block = 128;
    const int grid = total_threads / block;           // 12288
    median3x3_kernel<<<grid, block>>>(x, out);
}